// round 1
// baseline (speedup 1.0000x reference)
#include <cuda_runtime.h>
#include <cstddef>

// Problem dims
#define CB 2048   // batch
#define CT 64     // frames
#define CZ 64     // z dim
#define CH 512    // hidden
#define CH4 2048  // 4*H
#define BTZ (CB*CT*CZ)

// ---------------- device scratch (no allocations allowed) ----------------
__device__ float g_h1[CB*CH];
__device__ float g_c1[CB*CH];
__device__ float g_h2[CB*CH];
__device__ float g_c2[CB*CH];
__device__ float g_gates[CB*CH4];
__device__ float g_mv[CB*128];          // [mean(64) | logvar(64)] per row
__device__ float g_Whead[128*CH];       // packed [W_mean; W_logvar]
__device__ float g_bhead[128];

__device__ __forceinline__ float sigmoidf_(float x){ return 1.f/(1.f+__expf(-x)); }

// ---------------- init / pack ----------------
__global__ void zero_state_kernel(){
    int i = blockIdx.x*blockDim.x + threadIdx.x;
    if (i < CB*CH) { g_h1[i]=0.f; g_c1[i]=0.f; g_h2[i]=0.f; g_c2[i]=0.f; }
}

__global__ void pack_head_kernel(const float* __restrict__ Wm, const float* __restrict__ bm,
                                 const float* __restrict__ Wl, const float* __restrict__ bl){
    int i = blockIdx.x*blockDim.x + threadIdx.x;
    if (i < CZ*CH) { g_Whead[i] = Wm[i]; g_Whead[CZ*CH + i] = Wl[i]; }
    if (i < CZ)    { g_bhead[i] = bm[i]; g_bhead[CZ + i]    = bl[i]; }
}

// ---------------- generic NT GEMM with dual-source A (K-concat) and dual W ----
// C[m][n] = sum_{k<K0} A0[m][k]*W0[n][k] + sum_{k<K1} A1[m][k]*W1[n][k] + b0[n] (+ b1[n])
// A0 may be null -> zeros (t==0 case). A1 row stride = K1. W row-major [N, K*].
template<int BM,int BN,int BK,int TM,int TN>
__global__ __launch_bounds__((BM/TM)*(BN/TN))
void gemm_nt(const float* __restrict__ A0, int lda0, int K0,
             const float* __restrict__ A1, int K1,
             const float* __restrict__ W0, const float* __restrict__ W1,
             const float* __restrict__ b0, const float* __restrict__ b1,
             float* __restrict__ C, int N)
{
    constexpr int NT = (BM/TM)*(BN/TN);
    constexpr int TX = BN/TN;
    __shared__ float As[BK][BM+4];
    __shared__ float Ws[BK][BN+4];
    const int tid = threadIdx.x;
    const int tx = tid % TX, ty = tid / TX;
    const int m0 = blockIdx.y * BM;
    const int n0 = blockIdx.x * BN;
    const int Kt = K0 + K1;

    float acc[TM][TN];
#pragma unroll
    for (int i=0;i<TM;i++)
#pragma unroll
        for (int j=0;j<TN;j++) acc[i][j]=0.f;

    for (int k0 = 0; k0 < Kt; k0 += BK) {
        __syncthreads();  // prior compute done before smem overwrite
        for (int i = tid; i < BM*BK; i += NT) {
            int m = i / BK, k = i % BK;
            int kg = k0 + k;
            float v;
            if (kg < K0) v = A0 ? A0[(size_t)(m0+m)*lda0 + kg] : 0.f;
            else         v = A1[(size_t)(m0+m)*K1 + (kg-K0)];
            As[k][m] = v;
        }
        for (int i = tid; i < BN*BK; i += NT) {
            int n = i / BK, k = i % BK;
            int kg = k0 + k;
            float v;
            if (kg < K0) v = W0[(size_t)(n0+n)*K0 + kg];
            else         v = W1[(size_t)(n0+n)*K1 + (kg-K0)];
            Ws[k][n] = v;
        }
        __syncthreads();
#pragma unroll
        for (int kk=0; kk<BK; kk++){
            float af[TM], wf[TN];
#pragma unroll
            for (int i=0;i<TM;i++) af[i] = As[kk][ty*TM + i];
#pragma unroll
            for (int j=0;j<TN;j++) wf[j] = Ws[kk][tx*TN + j];
#pragma unroll
            for (int i=0;i<TM;i++)
#pragma unroll
                for (int j=0;j<TN;j++) acc[i][j] += af[i]*wf[j];
        }
    }

#pragma unroll
    for (int j=0;j<TN;j++){
        int n = n0 + tx*TN + j;
        float bias = b0[n] + (b1 ? b1[n] : 0.f);
#pragma unroll
        for (int i=0;i<TM;i++){
            int m = m0 + ty*TM + i;
            C[(size_t)m*N + n] = acc[i][j] + bias;
        }
    }
}

// ---------------- LSTM cell elementwise ----------------
__global__ void lstm_cell_kernel(const float* __restrict__ gates,
                                 float* __restrict__ h, float* __restrict__ c){
    int idx = blockIdx.x*blockDim.x + threadIdx.x;
    if (idx >= CB*CH) return;
    int m = idx / CH, j = idx % CH;
    const float* g = gates + (size_t)m*CH4;
    float ig = sigmoidf_(g[j]);
    float fg = sigmoidf_(g[CH + j]);
    float gg = tanhf(g[2*CH + j]);
    float og = sigmoidf_(g[3*CH + j]);
    float cn = fg * c[idx] + ig * gg;
    c[idx] = cn;
    h[idx] = og * tanhf(cn);
}

// ---------------- reparameterize + scatter outputs ----------------
__global__ void head_finish_kernel(int t, const float* __restrict__ eps,
                                   float* __restrict__ out){
    int idx = blockIdx.x*blockDim.x + threadIdx.x;
    if (idx >= CB*CZ) return;
    int m = idx / CZ, z = idx % CZ;
    float mean = g_mv[m*128 + z];
    float lv   = g_mv[m*128 + 64 + z];
    size_t o = (size_t)(m*CT + t)*CZ + z;
    float zv = mean + eps[o] * __expf(0.5f*lv);
    out[o]           = mean;
    out[BTZ + o]     = lv;
    out[2*(size_t)BTZ + o] = zv;
}

// ---------------- launch ----------------
extern "C" void kernel_launch(void* const* d_in, const int* in_sizes, int n_in,
                              void* d_out, int out_size){
    const float* z_post = (const float*)d_in[0];
    const float* eps    = (const float*)d_in[1];
    const float* W_ih1  = (const float*)d_in[2];
    const float* W_hh1  = (const float*)d_in[3];
    const float* b_ih1  = (const float*)d_in[4];
    const float* b_hh1  = (const float*)d_in[5];
    const float* W_ih2  = (const float*)d_in[6];
    const float* W_hh2  = (const float*)d_in[7];
    const float* b_ih2  = (const float*)d_in[8];
    const float* b_hh2  = (const float*)d_in[9];
    const float* W_mean = (const float*)d_in[10];
    const float* b_mean = (const float*)d_in[11];
    const float* W_lv   = (const float*)d_in[12];
    const float* b_lv   = (const float*)d_in[13];
    float* out = (float*)d_out;

    static float *h1=nullptr,*c1=nullptr,*h2=nullptr,*c2=nullptr,
                 *gates=nullptr,*mv=nullptr,*Whead=nullptr,*bhead=nullptr;
    if (!h1){
        cudaGetSymbolAddress((void**)&h1,    g_h1);
        cudaGetSymbolAddress((void**)&c1,    g_c1);
        cudaGetSymbolAddress((void**)&h2,    g_h2);
        cudaGetSymbolAddress((void**)&c2,    g_c2);
        cudaGetSymbolAddress((void**)&gates, g_gates);
        cudaGetSymbolAddress((void**)&mv,    g_mv);
        cudaGetSymbolAddress((void**)&Whead, g_Whead);
        cudaGetSymbolAddress((void**)&bhead, g_bhead);
    }

    zero_state_kernel<<<(CB*CH + 255)/256, 256>>>();
    pack_head_kernel<<<(CZ*CH + 255)/256, 256>>>(W_mean, b_mean, W_lv, b_lv);

    const dim3 gemm_grid(CH4/128, CB/128);     // (16,16)
    const dim3 head_grid(1, CB/16);            // 128 blocks
    const int cell_blocks = (CB*CH + 255)/256;
    const int hz_blocks   = (CB*CZ + 255)/256;

    for (int t = 0; t < CT; t++){
        const float* x = (t == 0) ? nullptr : (z_post + (size_t)(t-1)*CZ);
        // layer 1: gates = [x | h1] @ [W_ih1; W_hh1]^T + b
        gemm_nt<128,128,8,8,8><<<gemm_grid, 256>>>(
            x, CT*CZ, CZ, h1, CH, W_ih1, W_hh1, b_ih1, b_hh1, gates, CH4);
        lstm_cell_kernel<<<cell_blocks, 256>>>(gates, h1, c1);
        // layer 2: gates = [h1 | h2] @ [W_ih2; W_hh2]^T + b
        gemm_nt<128,128,8,8,8><<<gemm_grid, 256>>>(
            h1, CH, CH, h2, CH, W_ih2, W_hh2, b_ih2, b_hh2, gates, CH4);
        lstm_cell_kernel<<<cell_blocks, 256>>>(gates, h2, c2);
        // head: mv = h2 @ Whead^T + bhead   (N=128 = mean|logvar)
        gemm_nt<16,128,8,1,8><<<head_grid, 256>>>(
            h2, CH, CH, (const float*)nullptr, 0, Whead, (const float*)nullptr,
            bhead, (const float*)nullptr, mv, 128);
        head_finish_kernel<<<hz_blocks, 256>>>(t, eps, out);
    }
}

// round 3
// speedup vs baseline: 3.9323x; 3.9323x over previous
#include <cuda_runtime.h>
#include <cuda_bf16.h>
#include <cstdint>
#include <cstddef>

#define CB 2048
#define CT 64
#define CZ 64
#define CH 512
#define CH4 2048
#define BTZ (CB*CT*CZ)

// ---------------- persistent device buffers (no allocation allowed) ----------------
__device__ __nv_bfloat16 g_h1h[2][CB*CH], g_h1l[2][CB*CH];
__device__ __nv_bfloat16 g_h2h[2][CB*CH], g_h2l[2][CB*CH];
__device__ float g_c1[CB*CH], g_c2[CB*CH];
__device__ __nv_bfloat16 g_zph[BTZ], g_zpl[BTZ];
__device__ __nv_bfloat16 g_W1h[CH4*576],  g_W1l[CH4*576];
__device__ __nv_bfloat16 g_W2h[CH4*1024], g_W2l[CH4*1024];
__device__ __nv_bfloat16 g_Whdh[128*CH],  g_Whdl[128*CH];
__device__ __nv_bfloat16 g_zrow[64];   // zero-initialized

// ---------------- helpers ----------------
__device__ __forceinline__ uint32_t smem_u32(const void* p){
    uint32_t a;
    asm("{ .reg .u64 t; cvta.to.shared.u64 t, %1; cvt.u32.u64 %0, t; }" : "=r"(a) : "l"(p));
    return a;
}
#define SWZ(o) ((uint32_t)(o) ^ ((((uint32_t)(o))>>3)&0x70))
#define CP16(dst, src) asm volatile("cp.async.cg.shared.global [%0], [%1], 16;" :: "r"(dst), "l"(src) : "memory")
#define CP_COMMIT()    asm volatile("cp.async.commit_group;" ::: "memory")
template<int N> __device__ __forceinline__ void cp_wait(){
    asm volatile("cp.async.wait_group %0;" :: "n"(N) : "memory");
}
__device__ __forceinline__ void ldm4(uint32_t* r, uint32_t addr){
    asm volatile("ldmatrix.sync.aligned.m8n8.x4.shared.b16 {%0,%1,%2,%3}, [%4];"
        : "=r"(r[0]),"=r"(r[1]),"=r"(r[2]),"=r"(r[3]) : "r"(addr));
}
__device__ __forceinline__ void mma16816(float* c, const uint32_t* a, uint32_t b0, uint32_t b1){
    asm volatile("mma.sync.aligned.m16n8k16.row.col.f32.bf16.bf16.f32 "
        "{%0,%1,%2,%3}, {%4,%5,%6,%7}, {%8,%9}, {%0,%1,%2,%3};"
        : "+f"(c[0]),"+f"(c[1]),"+f"(c[2]),"+f"(c[3])
        : "r"(a[0]),"r"(a[1]),"r"(a[2]),"r"(a[3]), "r"(b0),"r"(b1));
}
__device__ __forceinline__ float sigm(float x){ return 1.f/(1.f+__expf(-x)); }
__device__ __forceinline__ void split1(float v, __nv_bfloat16 &hi, __nv_bfloat16 &lo){
    hi = __float2bfloat16_rn(v);
    lo = __float2bfloat16_rn(v - __bfloat162float(hi));
}

// ---------------- prepack kernels ----------------
__global__ void pack_zp_kernel(const float* __restrict__ zp){
    for (int i = blockIdx.x*blockDim.x + threadIdx.x; i < BTZ; i += gridDim.x*blockDim.x){
        __nv_bfloat16 h,l; split1(zp[i], h, l);
        g_zph[i]=h; g_zpl[i]=l;
    }
}
__global__ void pack_w1_kernel(const float* __restrict__ Wih, const float* __restrict__ Whh){
    for (int i = blockIdx.x*blockDim.x + threadIdx.x; i < CH4*576; i += gridDim.x*blockDim.x){
        int n = i/576, k = i%576;
        int srow = (n&3)*CH + (n>>2);
        float v = (k<64) ? Wih[(size_t)srow*64 + k] : Whh[(size_t)srow*CH + (k-64)];
        __nv_bfloat16 h,l; split1(v,h,l);
        g_W1h[i]=h; g_W1l[i]=l;
    }
}
__global__ void pack_w2_kernel(const float* __restrict__ Wih, const float* __restrict__ Whh){
    for (int i = blockIdx.x*blockDim.x + threadIdx.x; i < CH4*1024; i += gridDim.x*blockDim.x){
        int n = i>>10, k = i&1023;
        int srow = (n&3)*CH + (n>>2);
        float v = (k<512) ? Wih[(size_t)srow*CH + k] : Whh[(size_t)srow*CH + (k-512)];
        __nv_bfloat16 h,l; split1(v,h,l);
        g_W2h[i]=h; g_W2l[i]=l;
    }
}
__global__ void pack_whd_kernel(const float* __restrict__ Wm, const float* __restrict__ Wlv){
    for (int i = blockIdx.x*blockDim.x + threadIdx.x; i < 128*CH; i += gridDim.x*blockDim.x){
        int n = i>>9, k = i&511;
        int z = n>>1;
        float v = (n&1) ? Wlv[(size_t)z*CH + k] : Wm[(size_t)z*CH + k];
        __nv_bfloat16 h,l; split1(v,h,l);
        g_Whdh[i]=h; g_Whdl[i]=l;
    }
}
__global__ void zero_state_kernel(){
    int i = blockIdx.x*blockDim.x + threadIdx.x;
    if (i < CB*CH){
        __nv_bfloat16 z = __float2bfloat16_rn(0.f);
        g_h1h[0][i]=z; g_h1l[0][i]=z; g_h2h[0][i]=z; g_h2l[0][i]=z;
        g_c1[i]=0.f; g_c2[i]=0.f;
    }
}

// ---------------- layer kernel: CTA 128x256, 512 thr, fused LSTM cell ----------------
// stage: Ah 0 (16K) | Al 16384 | Wh 32768 (32K) | Wl 65536  => 96K, x2 stages
#define L_STAGE 98304
#define L_SMEM  (1024 + 2*L_STAGE)

__global__ __launch_bounds__(512,1)
void lstm_layer(const __nv_bfloat16* __restrict__ A0h, const __nv_bfloat16* __restrict__ A0l, int a0str,
                const __nv_bfloat16* __restrict__ A1h, const __nv_bfloat16* __restrict__ A1l,
                const __nv_bfloat16* __restrict__ Wh,  const __nv_bfloat16* __restrict__ Wl, int Kw,
                const float* __restrict__ bih, const float* __restrict__ bhh,
                __nv_bfloat16* __restrict__ Hh, __nv_bfloat16* __restrict__ Hl,
                float* __restrict__ Cst, int k0ch, int nch)
{
    extern __shared__ char smem[];
    const uint32_t sb = smem_u32(smem);
    float* bias_s = (float*)smem;
    const int tid = threadIdx.x, wid = tid>>5, lid = tid&31;
    const int m0 = blockIdx.y*128, n0 = blockIdx.x*256;
    const int m_w = (wid>>3)*64, n_w = (wid&7)*32;
    const int lr = lid&7, q = lid>>3;
    const int rofs = (q&1)*8 + lr, cofs = (q>>1)*16;

    if (tid < 256){
        int ng = n0 + tid; int srow = (ng&3)*CH + (ng>>2);
        bias_s[tid] = bih[srow] + bhh[srow];
    }

    auto issue = [&](int ch){
        const uint32_t st = sb + 1024 + (uint32_t)(ch&1)*L_STAGE;
        const int k0 = ch*64;
        // A tile 128x64 hi/lo
        #pragma unroll
        for (int p = tid; p < 2048; p += 512){
            int half = p>>10, qq = p&1023, r = qq>>3, u = qq&7;
            const __nv_bfloat16* base; int astr; int kl;
            if (ch < k0ch){ base = half? A0l : A0h; astr = a0str; kl = k0; }
            else          { base = half? A1l : A1h; astr = CH;    kl = k0 - k0ch*64; }
            const char* src = (const char*)base + ((size_t)(m0+r)*astr + kl)*2 + u*16;
            CP16(st + half*16384u + SWZ(r*128 + u*16), src);
        }
        // W tile 256x64 hi/lo
        #pragma unroll
        for (int p = tid; p < 4096; p += 512){
            int half = p>>11, qq = p&2047, r = qq>>3, u = qq&7;
            const __nv_bfloat16* base = half? Wl : Wh;
            const char* src = (const char*)base + ((size_t)(n0+r)*Kw + k0)*2 + u*16;
            CP16(st + 32768u + half*32768u + SWZ(r*128 + u*16), src);
        }
        CP_COMMIT();
    };

    float acc[4][4][4];
    #pragma unroll
    for (int a=0;a<4;a++)
    #pragma unroll
    for (int b=0;b<4;b++)
    #pragma unroll
    for (int c=0;c<4;c++) acc[a][b][c]=0.f;

    issue(0);
    for (int ch = 0; ch < nch; ch++){
        if (ch+1 < nch){ issue(ch+1); cp_wait<1>(); }
        else           { cp_wait<0>(); }
        __syncthreads();
        const uint32_t st  = sb + 1024 + (uint32_t)(ch&1)*L_STAGE;
        const uint32_t stAh = st, stAl = st+16384u, stWh = st+32768u, stWl = st+65536u;
        // pass 1: Ah x (Wh, Wl)
        #pragma unroll
        for (int kk=0; kk<4; kk++){
            uint32_t a[4][4], wh[2][4], wl[2][4];
            #pragma unroll
            for (int mt=0; mt<4; mt++)
                ldm4(a[mt], stAh + SWZ((m_w+mt*16+rofs)*128 + kk*32 + cofs));
            #pragma unroll
            for (int g=0; g<2; g++){
                ldm4(wh[g], stWh + SWZ((n_w+g*16+rofs)*128 + kk*32 + cofs));
                ldm4(wl[g], stWl + SWZ((n_w+g*16+rofs)*128 + kk*32 + cofs));
            }
            #pragma unroll
            for (int mt=0; mt<4; mt++)
            #pragma unroll
            for (int nt=0; nt<4; nt++){
                mma16816(acc[mt][nt], a[mt], wh[nt>>1][nt&1], wh[nt>>1][(nt&1)+2]);
                mma16816(acc[mt][nt], a[mt], wl[nt>>1][nt&1], wl[nt>>1][(nt&1)+2]);
            }
        }
        // pass 2: Al x Wh
        #pragma unroll
        for (int kk=0; kk<4; kk++){
            uint32_t a[4][4], wh[2][4];
            #pragma unroll
            for (int mt=0; mt<4; mt++)
                ldm4(a[mt], stAl + SWZ((m_w+mt*16+rofs)*128 + kk*32 + cofs));
            #pragma unroll
            for (int g=0; g<2; g++)
                ldm4(wh[g], stWh + SWZ((n_w+g*16+rofs)*128 + kk*32 + cofs));
            #pragma unroll
            for (int mt=0; mt<4; mt++)
            #pragma unroll
            for (int nt=0; nt<4; nt++)
                mma16816(acc[mt][nt], a[mt], wh[nt>>1][nt&1], wh[nt>>1][(nt&1)+2]);
        }
        __syncthreads();
    }

    // ---- fused LSTM-cell epilogue ----
    const int gr = lid>>2, cid = lid&3;
    #pragma unroll
    for (int mt=0; mt<4; mt++)
    #pragma unroll
    for (int nt=0; nt<4; nt++){
        float c0=acc[mt][nt][0], c1=acc[mt][nt][1], c2=acc[mt][nt][2], c3=acc[mt][nt][3];
        float p0=__shfl_xor_sync(0xffffffffu,c0,1), p1=__shfl_xor_sync(0xffffffffu,c1,1);
        float p2=__shfl_xor_sync(0xffffffffu,c2,1), p3=__shfl_xor_sync(0xffffffffu,c3,1);
        int nb = n_w + nt*8 + 4*(cid>>1);
        float bi=bias_s[nb+0], bf=bias_s[nb+1], bg=bias_s[nb+2], bo=bias_s[nb+3];
        int row; float gi,gf,gg,go;
        if ((cid&1)==0){ row = gr;   gi=c0; gf=c1; gg=p0; go=p1; }
        else           { row = gr+8; gi=p2; gf=p3; gg=c2; go=c3; }
        int m = m0 + m_w + mt*16 + row;
        int j = (n0 + nb)>>2;
        size_t idx = (size_t)m*CH + j;
        float cn = sigm(gf+bf)*Cst[idx] + sigm(gi+bi)*tanhf(gg+bg);
        Cst[idx] = cn;
        float h = sigm(go+bo)*tanhf(cn);
        __nv_bfloat16 hh, hl; split1(h, hh, hl);
        Hh[idx]=hh; Hl[idx]=hl;
    }
}

// ---------------- head kernel: CTA 32x128, 128 thr, reparameterize epilogue ----------------
// stage: Ah 0 (4K) | Al 4096 | Wh 8192 (16K) | Wl 24576 => 40K, x2
#define H_STAGE 40960
#define H_SMEM  (1024 + 2*H_STAGE)

__global__ __launch_bounds__(128,1)
void head_kernel(const __nv_bfloat16* __restrict__ Ah_, const __nv_bfloat16* __restrict__ Al_,
                 const float* __restrict__ bm, const float* __restrict__ blv,
                 const float* __restrict__ eps, float* __restrict__ out, int t)
{
    extern __shared__ char smem[];
    const uint32_t sb = smem_u32(smem);
    float* bias_s = (float*)smem;
    const int tid = threadIdx.x, wid = tid>>5, lid = tid&31;
    const int m0 = blockIdx.y*32;
    const int m_w = (wid>>1)*16, n_w = (wid&1)*64;
    const int lr = lid&7, q = lid>>3;
    const int rofs = (q&1)*8 + lr, cofs = (q>>1)*16;

    if (tid < 128){
        int z = tid>>1;
        bias_s[tid] = (tid&1) ? blv[z] : bm[z];
    }

    auto issue = [&](int ch){
        const uint32_t st = sb + 1024 + (uint32_t)(ch&1)*H_STAGE;
        const int k0 = ch*64;
        #pragma unroll
        for (int p = tid; p < 512; p += 128){
            int half = p>>8, qq = p&255, r = qq>>3, u = qq&7;
            const __nv_bfloat16* base = half? Al_ : Ah_;
            const char* src = (const char*)base + ((size_t)(m0+r)*CH + k0)*2 + u*16;
            CP16(st + half*4096u + SWZ(r*128 + u*16), src);
        }
        #pragma unroll
        for (int p = tid; p < 2048; p += 128){
            int half = p>>10, qq = p&1023, r = qq>>3, u = qq&7;
            const __nv_bfloat16* base = half? g_Whdl : g_Whdh;
            const char* src = (const char*)base + ((size_t)r*CH + k0)*2 + u*16;
            CP16(st + 8192u + half*16384u + SWZ(r*128 + u*16), src);
        }
        CP_COMMIT();
    };

    float acc[8][4];
    #pragma unroll
    for (int a=0;a<8;a++)
    #pragma unroll
    for (int c=0;c<4;c++) acc[a][c]=0.f;

    issue(0);
    const int nch = 8;
    for (int ch = 0; ch < nch; ch++){
        if (ch+1 < nch){ issue(ch+1); cp_wait<1>(); }
        else           { cp_wait<0>(); }
        __syncthreads();
        const uint32_t st  = sb + 1024 + (uint32_t)(ch&1)*H_STAGE;
        const uint32_t stAh = st, stAl = st+4096u, stWh = st+8192u, stWl = st+24576u;
        #pragma unroll
        for (int kk=0; kk<4; kk++){
            uint32_t a[4], wh[4][4], wl[4][4];
            ldm4(a, stAh + SWZ((m_w+rofs)*128 + kk*32 + cofs));
            #pragma unroll
            for (int g=0; g<4; g++){
                ldm4(wh[g], stWh + SWZ((n_w+g*16+rofs)*128 + kk*32 + cofs));
                ldm4(wl[g], stWl + SWZ((n_w+g*16+rofs)*128 + kk*32 + cofs));
            }
            #pragma unroll
            for (int nt=0; nt<8; nt++){
                mma16816(acc[nt], a, wh[nt>>1][nt&1], wh[nt>>1][(nt&1)+2]);
                mma16816(acc[nt], a, wl[nt>>1][nt&1], wl[nt>>1][(nt&1)+2]);
            }
        }
        #pragma unroll
        for (int kk=0; kk<4; kk++){
            uint32_t a[4], wh[4][4];
            ldm4(a, stAl + SWZ((m_w+rofs)*128 + kk*32 + cofs));
            #pragma unroll
            for (int g=0; g<4; g++)
                ldm4(wh[g], stWh + SWZ((n_w+g*16+rofs)*128 + kk*32 + cofs));
            #pragma unroll
            for (int nt=0; nt<8; nt++)
                mma16816(acc[nt], a, wh[nt>>1][nt&1], wh[nt>>1][(nt&1)+2]);
        }
        __syncthreads();
    }

    const int gr = lid>>2, cid = lid&3;
    #pragma unroll
    for (int nt=0; nt<8; nt++){
        int nb = n_w + nt*8 + 2*cid;
        int z = nb>>1;
        float bmv = bias_s[nb], blvv = bias_s[nb+1];
        // row gr
        {
            int m = m0 + m_w + gr;
            float mean = acc[nt][0] + bmv;
            float lv   = acc[nt][1] + blvv;
            size_t o = ((size_t)m*CT + t)*CZ + z;
            out[o] = mean;
            out[(size_t)BTZ + o] = lv;
            out[2*(size_t)BTZ + o] = mean + eps[o]*__expf(0.5f*lv);
        }
        // row gr+8
        {
            int m = m0 + m_w + gr + 8;
            float mean = acc[nt][2] + bmv;
            float lv   = acc[nt][3] + blvv;
            size_t o = ((size_t)m*CT + t)*CZ + z;
            out[o] = mean;
            out[(size_t)BTZ + o] = lv;
            out[2*(size_t)BTZ + o] = mean + eps[o]*__expf(0.5f*lv);
        }
    }
}

// ---------------- launch ----------------
extern "C" void kernel_launch(void* const* d_in, const int* in_sizes, int n_in,
                              void* d_out, int out_size){
    const float* z_post = (const float*)d_in[0];
    const float* eps    = (const float*)d_in[1];
    const float* W_ih1  = (const float*)d_in[2];
    const float* W_hh1  = (const float*)d_in[3];
    const float* b_ih1  = (const float*)d_in[4];
    const float* b_hh1  = (const float*)d_in[5];
    const float* W_ih2  = (const float*)d_in[6];
    const float* W_hh2  = (const float*)d_in[7];
    const float* b_ih2  = (const float*)d_in[8];
    const float* b_hh2  = (const float*)d_in[9];
    const float* W_mean = (const float*)d_in[10];
    const float* b_mean = (const float*)d_in[11];
    const float* W_lv   = (const float*)d_in[12];
    const float* b_lv   = (const float*)d_in[13];
    float* out = (float*)d_out;

    static __nv_bfloat16 *h1h=nullptr,*h1l=nullptr,*h2h=nullptr,*h2l=nullptr,*zph=nullptr,*zpl=nullptr,*zrow=nullptr;
    static float *c1=nullptr,*c2=nullptr;
    if (!h1h){
        cudaGetSymbolAddress((void**)&h1h, g_h1h);
        cudaGetSymbolAddress((void**)&h1l, g_h1l);
        cudaGetSymbolAddress((void**)&h2h, g_h2h);
        cudaGetSymbolAddress((void**)&h2l, g_h2l);
        cudaGetSymbolAddress((void**)&zph, g_zph);
        cudaGetSymbolAddress((void**)&zpl, g_zpl);
        cudaGetSymbolAddress((void**)&zrow, g_zrow);
        cudaGetSymbolAddress((void**)&c1,  g_c1);
        cudaGetSymbolAddress((void**)&c2,  g_c2);
        cudaFuncSetAttribute(lstm_layer, cudaFuncAttributeMaxDynamicSharedMemorySize, L_SMEM);
        cudaFuncSetAttribute(head_kernel, cudaFuncAttributeMaxDynamicSharedMemorySize, H_SMEM);
    }
    static __nv_bfloat16 *w1h=nullptr,*w1l=nullptr,*w2h=nullptr,*w2l=nullptr;
    if (!w1h){
        cudaGetSymbolAddress((void**)&w1h, g_W1h);
        cudaGetSymbolAddress((void**)&w1l, g_W1l);
        cudaGetSymbolAddress((void**)&w2h, g_W2h);
        cudaGetSymbolAddress((void**)&w2l, g_W2l);
    }

    pack_zp_kernel<<<2048, 256>>>(z_post);
    pack_w1_kernel<<<1024, 256>>>(W_ih1, W_hh1);
    pack_w2_kernel<<<2048, 256>>>(W_ih2, W_hh2);
    pack_whd_kernel<<<256, 256>>>(W_mean, W_lv);
    zero_state_kernel<<<(CB*CH + 255)/256, 256>>>();

    const dim3 lgrid(8, 16);   // n tiles, m tiles
    const dim3 hgrid(1, 64);
    for (int t = 0; t < CT; t++){
        const int r = t & 1, w = r ^ 1;
        const __nv_bfloat16* x_h; const __nv_bfloat16* x_l; int xstr;
        if (t == 0){ x_h = zrow; x_l = zrow; xstr = 0; }
        else { x_h = zph + (size_t)(t-1)*CZ; x_l = zpl + (size_t)(t-1)*CZ; xstr = CT*CZ; }
        __nv_bfloat16* h1rh = h1h + (size_t)r*CB*CH; __nv_bfloat16* h1rl = h1l + (size_t)r*CB*CH;
        __nv_bfloat16* h1wh = h1h + (size_t)w*CB*CH; __nv_bfloat16* h1wl = h1l + (size_t)w*CB*CH;
        __nv_bfloat16* h2rh = h2h + (size_t)r*CB*CH; __nv_bfloat16* h2rl = h2l + (size_t)r*CB*CH;
        __nv_bfloat16* h2wh = h2h + (size_t)w*CB*CH; __nv_bfloat16* h2wl = h2l + (size_t)w*CB*CH;

        lstm_layer<<<lgrid, 512, L_SMEM>>>(
            x_h, x_l, xstr, h1rh, h1rl, w1h, w1l, 576,
            b_ih1, b_hh1, h1wh, h1wl, c1, 1, 9);
        lstm_layer<<<lgrid, 512, L_SMEM>>>(
            h1wh, h1wl, CH, h2rh, h2rl, w2h, w2l, 1024,
            b_ih2, b_hh2, h2wh, h2wl, c2, 8, 16);
        head_kernel<<<hgrid, 128, H_SMEM>>>(
            h2wh, h2wl, b_mean, b_lv, eps, out, t);
    }
}